// round 8
// baseline (speedup 1.0000x reference)
#include <cuda_runtime.h>
#include <cuda_fp16.h>
#include <mma.h>

using namespace nvcuda;

#define NN 500000
#define EE 2000000
#define GG 64
#define EPS 1e-5f
#define SCAN_B 512
#define NBS ((NN + SCAN_B - 1) / SCAN_B)   // 977

// ---------------- scratch (device globals; no allocs allowed) ----------------
__device__ __align__(16) int    g_deg[NN];
__device__ __align__(16) float  g_dis[NN];
__device__ __align__(16) int    g_c[NN];
__device__ __align__(16) int    g_off[NN + 1];
__device__ __align__(16) int    g_cur[NN];
__device__ __align__(16) int    g_bsum[NBS];
__device__ __align__(16) int    g_bpre[NBS];
__device__ __align__(16) int    g_srcs[EE];
__device__ __align__(16) float  g_S[NN * 9];
__device__ __align__(16) __half g_y1[((size_t)NN + 128) * 64];  // dis*(z1@W2) fp16
__device__ __align__(16) __half g_y[(size_t)NN * 64];           // aggregated layer-2 out
__device__ __align__(16) float  g_M1[9 * 64];
__device__ __align__(16) float  g_a1[64];
__device__ __align__(16) float  g_sh1[64];
__device__ __align__(16) float  g_mom[64];
__device__ __align__(16) float  g_s2[64];
__device__ __align__(16) float  g_q2[64];
__device__ __align__(16) float  g_psum[GG * 64];
__device__ __align__(16) int    g_pmax[GG * 64];
__device__ __align__(16) int    g_pmin[GG * 64];
__device__                int    g_cnt[GG];

// ---------------- helpers ----------------
__device__ __forceinline__ void atomicMaxFloat(int* addr, float v) {
    if (v >= 0.0f) atomicMax(addr, __float_as_int(v));
    else           atomicMin((unsigned int*)addr, __float_as_uint(v));
}
__device__ __forceinline__ void atomicMinFloat(int* addr, float v) {
    if (v >= 0.0f) atomicMin(addr, __float_as_int(v));
    else           atomicMax((unsigned int*)addr, __float_as_uint(v));
}

// ---------------- small init ----------------
__global__ void k_small_init() {
    int i = blockIdx.x * blockDim.x + threadIdx.x;
    if (i < GG * 64) {
        g_pmax[i] = 0xFF800000;
        g_pmin[i] = 0x7F800000;
        g_psum[i] = 0.0f;
    }
    if (i < 64) {
        g_mom[i] = 0.0f;
        g_s2[i] = 0.0f; g_q2[i] = 0.0f;
    }
}

// ---------------- per-graph node counts: binary search over sorted batch -----
__global__ void k_cnt(const int* __restrict__ batch) {
    int g = threadIdx.x;
    if (g >= GG) return;
    int lo0 = 0, hi0 = NN;
    while (lo0 < hi0) { int m = (lo0 + hi0) >> 1; if (batch[m] < g) lo0 = m + 1; else hi0 = m; }
    int lo1 = lo0, hi1 = NN;
    while (lo1 < hi1) { int m = (lo1 + hi1) >> 1; if (batch[m] < g + 1) lo1 = m + 1; else hi1 = m; }
    g_cnt[g] = lo1 - lo0;
}

// ---------------- M1 = [emb_type || emb_inv] @ W1  (9 x 64) ----------------
__global__ void k_prep(const float* __restrict__ emb_type,
                       const float* __restrict__ emb_inv,
                       const float* __restrict__ W1) {
    int t = threadIdx.x;
    if (t >= 9 * 64) return;
    int combo = t >> 6;
    int f = t & 63;
    int ty = combo / 3, iv = combo % 3;
    float acc = 0.0f;
#pragma unroll
    for (int k = 0; k < 16; k++) {
        acc = fmaf(emb_type[ty * 16 + k], W1[k * 64 + f], acc);
        acc = fmaf(emb_inv[iv * 16 + k], W1[(16 + k) * 64 + f], acc);
    }
    g_M1[combo * 64 + f] = acc;
}

// ---------------- degree histogram ----------------
__global__ void k_deg(const int* __restrict__ edst) {
    int e = blockIdx.x * blockDim.x + threadIdx.x;
    if (e < EE) atomicAdd(&g_deg[edst[e]], 1);
}

// ---------------- per-node: dis, combo idx, write full S row ----------------
__global__ void k_dis(const int* __restrict__ node_type,
                      const int* __restrict__ num_inv) {
    int v = blockIdx.x * blockDim.x + threadIdx.x;
    if (v >= NN) return;
    int d = g_deg[v] + 1;
    float dis = rsqrtf((float)d);
    g_dis[v] = dis;
    int c = node_type[v] * 3 + num_inv[v];
    g_c[v] = c;
    float id = dis * dis;
#pragma unroll
    for (int t = 0; t < 9; t++) g_S[(size_t)v * 9 + t] = (t == c) ? id : 0.0f;
}

// ---------------- CSR scan (3 stages) ----------------
__global__ __launch_bounds__(SCAN_B) void k_scan1() {
    __shared__ int s[SCAN_B];
    int gid = blockIdx.x * SCAN_B + threadIdx.x;
    int v = (gid < NN) ? g_deg[gid] : 0;
    s[threadIdx.x] = v;
    __syncthreads();
    for (int o = 1; o < SCAN_B; o <<= 1) {
        int x = s[threadIdx.x];
        if (threadIdx.x >= o) x += s[threadIdx.x - o];
        __syncthreads();
        s[threadIdx.x] = x;
        __syncthreads();
    }
    if (threadIdx.x == SCAN_B - 1) g_bsum[blockIdx.x] = s[SCAN_B - 1];
}
__global__ __launch_bounds__(1024) void k_scan2() {
    __shared__ int s[1024];
    int t = threadIdx.x;
    int v = (t < NBS) ? g_bsum[t] : 0;
    s[t] = v;
    __syncthreads();
    for (int o = 1; o < 1024; o <<= 1) {
        int x = s[t];
        if (t >= o) x += s[t - o];
        __syncthreads();
        s[t] = x;
        __syncthreads();
    }
    if (t < NBS) g_bpre[t] = s[t] - v;   // exclusive
}
__global__ __launch_bounds__(SCAN_B) void k_scan3() {
    __shared__ int s[SCAN_B];
    int gid = blockIdx.x * SCAN_B + threadIdx.x;
    int v = (gid < NN) ? g_deg[gid] : 0;
    s[threadIdx.x] = v;
    __syncthreads();
    for (int o = 1; o < SCAN_B; o <<= 1) {
        int x = s[threadIdx.x];
        if (threadIdx.x >= o) x += s[threadIdx.x - o];
        __syncthreads();
        s[threadIdx.x] = x;
        __syncthreads();
    }
    if (gid < NN) {
        int excl = s[threadIdx.x] - v + g_bpre[blockIdx.x];
        g_off[gid] = excl;
        g_cur[gid] = excl;
        if (gid == NN - 1) g_off[NN] = excl + v;
    }
}

// ------- fused: CSR ticket-scatter + layer-1 bucket aggregation ---------------
__global__ void k_scatter_edge1(const int* __restrict__ esrc, const int* __restrict__ edst) {
    int e = blockIdx.x * blockDim.x + threadIdx.x;
    if (e >= EE) return;
    int s = esrc[e], d = edst[e];
    int pos = atomicAdd(&g_cur[d], 1);
    g_srcs[pos] = s;
    atomicAdd(&g_S[(size_t)d * 9 + g_c[s]], g_dis[s] * g_dis[d]);
}

// ---------------- S moments: sum S (9) + upper-tri of sum S S^T (45) ----------
__global__ __launch_bounds__(256) void k_stats() {
    __shared__ float sS[256 * 9];
    __shared__ float sred[8][54];
    float m[54];
#pragma unroll
    for (int i = 0; i < 54; i++) m[i] = 0.0f;

    int tiles = (NN + 255) / 256;
    for (int t = blockIdx.x; t < tiles; t += gridDim.x) {
        int base = t * 256;
        int cnt = min(256, NN - base);
        int tot = cnt * 9;
        __syncthreads();
        for (int i = threadIdx.x; i < tot; i += 256) sS[i] = g_S[(size_t)base * 9 + i];
        __syncthreads();
        if ((int)threadIdx.x < cnt) {
            float r[9];
#pragma unroll
            for (int j = 0; j < 9; j++) r[j] = sS[threadIdx.x * 9 + j];
            int k = 9;
#pragma unroll
            for (int i = 0; i < 9; i++) {
                m[i] += r[i];
#pragma unroll
                for (int j = i; j < 9; j++) { m[k] = fmaf(r[i], r[j], m[k]); k++; }
            }
        }
    }
#pragma unroll
    for (int v = 0; v < 54; v++) {
#pragma unroll
        for (int o = 16; o > 0; o >>= 1) m[v] += __shfl_down_sync(0xffffffffu, m[v], o);
    }
    int lane = threadIdx.x & 31, warp = threadIdx.x >> 5;
    if (lane == 0) {
#pragma unroll
        for (int v = 0; v < 54; v++) sred[warp][v] = m[v];
    }
    __syncthreads();
    if (threadIdx.x < 54) {
        float acc = 0.0f;
#pragma unroll
        for (int w = 0; w < 8; w++) acc += sred[w][threadIdx.x];
        atomicAdd(&g_mom[threadIdx.x], acc);
    }
}

// ---------------- BN1 affine params from moments ----------------
__global__ void k_bn1(const float* __restrict__ gamma1, const float* __restrict__ beta1) {
    int f = threadIdx.x;
    if (f >= 64) return;
    float mcol[9];
#pragma unroll
    for (int t = 0; t < 9; t++) mcol[t] = g_M1[t * 64 + f];
    float mean = 0.0f;
#pragma unroll
    for (int t = 0; t < 9; t++) mean = fmaf(g_mom[t], mcol[t], mean);
    mean /= (float)NN;
    float e2 = 0.0f;
    int k = 9;
#pragma unroll
    for (int i = 0; i < 9; i++) {
#pragma unroll
        for (int j = i; j < 9; j++) {
            float term = g_mom[k++] * mcol[i] * mcol[j];
            e2 += (i == j) ? term : 2.0f * term;
        }
    }
    e2 /= (float)NN;
    float var = e2 - mean * mean;
    float a = rsqrtf(var + EPS) * gamma1[f];
    g_a1[f] = a;
    g_sh1[f] = beta1[f] - mean * a;
}

// -- fused layer1 + GEMM: (dis*z1) tile in smem fp16 -> wmma @ W2 -> y1' fp16 --
// y1'[v] = dis[v] * relu(affine(S@M1)) @ W2
#define ZLD 80
__global__ __launch_bounds__(256) void k_fused1(const float* __restrict__ W2) {
    __shared__ float  sM1[9 * 64];
    __shared__ float  sA[64], sSh[64];
    __shared__ __half sW[64 * 64];
    __shared__ __half sZ[128 * ZLD];

    int tid = threadIdx.x;
    for (int i = tid; i < 9 * 64; i += 256) sM1[i] = g_M1[i];
    if (tid < 64) { sA[tid] = g_a1[tid]; sSh[tid] = g_sh1[tid]; }
    for (int i = tid; i < 64 * 64 / 2; i += 256) {
        float2 w = ((const float2*)W2)[i];
        ((half2*)sW)[i] = __floats2half2_rn(w.x, w.y);
    }
    __syncthreads();

    int base = blockIdx.x * 128;
    {
        int nl = tid >> 1;
        int h = tid & 1;
        int v = base + nl;
        half2* dst = (half2*)(sZ + nl * ZLD + h * 32);
        if (v < NN) {
            float dv = g_dis[v];
            float Sv[9];
#pragma unroll
            for (int t = 0; t < 9; t++) Sv[t] = g_S[(size_t)v * 9 + t];
#pragma unroll
            for (int j = 0; j < 16; j++) {
                int f = h * 32 + 2 * j;
                float y0 = 0.f, y1 = 0.f;
#pragma unroll
                for (int t = 0; t < 9; t++) {
                    y0 = fmaf(Sv[t], sM1[t * 64 + f], y0);
                    y1 = fmaf(Sv[t], sM1[t * 64 + f + 1], y1);
                }
                float z0 = dv * fmaxf(fmaf(y0, sA[f], sSh[f]), 0.f);
                float z1 = dv * fmaxf(fmaf(y1, sA[f + 1], sSh[f + 1]), 0.f);
                dst[j] = __floats2half2_rn(z0, z1);
            }
        } else {
#pragma unroll
            for (int j = 0; j < 16; j++) dst[j] = __floats2half2_rn(0.f, 0.f);
        }
    }
    __syncthreads();

    int w = tid >> 5;
    wmma::fragment<wmma::accumulator, 16, 16, 16, float> cf[4];
#pragma unroll
    for (int n = 0; n < 4; n++) wmma::fill_fragment(cf[n], 0.0f);
#pragma unroll
    for (int k = 0; k < 4; k++) {
        wmma::fragment<wmma::matrix_a, 16, 16, 16, __half, wmma::row_major> af;
        wmma::load_matrix_sync(af, sZ + (w * 16) * ZLD + k * 16, ZLD);
#pragma unroll
        for (int n = 0; n < 4; n++) {
            wmma::fragment<wmma::matrix_b, 16, 16, 16, __half, wmma::row_major> bf;
            wmma::load_matrix_sync(bf, sW + (k * 16) * 64 + n * 16, 64);
            wmma::mma_sync(cf[n], af, bf, cf[n]);
        }
    }
#pragma unroll
    for (int n = 0; n < 4; n++) {
        wmma::fragment<wmma::accumulator, 16, 16, 16, __half> ch;
#pragma unroll
        for (int i = 0; i < cf[n].num_elements; i++) ch.x[i] = __float2half(cf[n].x[i]);
        wmma::store_matrix_sync(g_y1 + ((size_t)base + w * 16) * 64 + n * 16, ch, 64,
                                wmma::mem_row_major);
    }
}

// ---------- layer-2 aggregation: warp-per-node, 4 edges in flight -------------
// y[v] = dis[v] * ( y1'[v] + sum_{s in in(v)} y1'[s] )
__global__ __launch_bounds__(256) void k_gather() {
    int lane = threadIdx.x & 31;
    int sub = lane & 7;                  // 16B chunk (8 feats) of 128B fp16 row
    int eo = lane >> 3;                  // edge slot 0..3
    int gw = (blockIdx.x * blockDim.x + threadIdx.x) >> 5;
    int nw = (gridDim.x * blockDim.x) >> 5;

    for (int v = gw; v < NN; v += nw) {
        int off0 = g_off[v], off1 = g_off[v + 1];   // warp-broadcast loads
        float a0 = 0.f, a1 = 0.f, a2 = 0.f, a3 = 0.f;
        float a4 = 0.f, a5 = 0.f, a6 = 0.f, a7 = 0.f;
        if (eo == 0) {                    // self term joins the sum (scaled later)
            uint4 raw = ((const uint4*)(g_y1 + (size_t)v * 64))[sub];
            float2 p0 = __half22float2(*(half2*)&raw.x);
            float2 p1 = __half22float2(*(half2*)&raw.y);
            float2 p2 = __half22float2(*(half2*)&raw.z);
            float2 p3 = __half22float2(*(half2*)&raw.w);
            a0 = p0.x; a1 = p0.y; a2 = p1.x; a3 = p1.y;
            a4 = p2.x; a5 = p2.y; a6 = p3.x; a7 = p3.y;
        }
        for (int i = off0 + eo; i < off1; i += 4) {
            int s = g_srcs[i];
            uint4 r = ((const uint4*)(g_y1 + (size_t)s * 64))[sub];
            float2 q0 = __half22float2(*(half2*)&r.x);
            float2 q1 = __half22float2(*(half2*)&r.y);
            float2 q2 = __half22float2(*(half2*)&r.z);
            float2 q3 = __half22float2(*(half2*)&r.w);
            a0 += q0.x; a1 += q0.y; a2 += q1.x; a3 += q1.y;
            a4 += q2.x; a5 += q2.y; a6 += q3.x; a7 += q3.y;
        }
        // fold the 4 edge slots (lanes with equal sub differ in bits 3,4)
        a0 += __shfl_xor_sync(0xffffffffu, a0, 8);  a0 += __shfl_xor_sync(0xffffffffu, a0, 16);
        a1 += __shfl_xor_sync(0xffffffffu, a1, 8);  a1 += __shfl_xor_sync(0xffffffffu, a1, 16);
        a2 += __shfl_xor_sync(0xffffffffu, a2, 8);  a2 += __shfl_xor_sync(0xffffffffu, a2, 16);
        a3 += __shfl_xor_sync(0xffffffffu, a3, 8);  a3 += __shfl_xor_sync(0xffffffffu, a3, 16);
        a4 += __shfl_xor_sync(0xffffffffu, a4, 8);  a4 += __shfl_xor_sync(0xffffffffu, a4, 16);
        a5 += __shfl_xor_sync(0xffffffffu, a5, 8);  a5 += __shfl_xor_sync(0xffffffffu, a5, 16);
        a6 += __shfl_xor_sync(0xffffffffu, a6, 8);  a6 += __shfl_xor_sync(0xffffffffu, a6, 16);
        a7 += __shfl_xor_sync(0xffffffffu, a7, 8);  a7 += __shfl_xor_sync(0xffffffffu, a7, 16);
        if (eo == 0) {
            float dv = g_dis[v];
            half2 h0 = __floats2half2_rn(dv * a0, dv * a1);
            half2 h1 = __floats2half2_rn(dv * a2, dv * a3);
            half2 h2 = __floats2half2_rn(dv * a4, dv * a5);
            half2 h3 = __floats2half2_rn(dv * a6, dv * a7);
            uint4 out;
            out.x = *(unsigned*)&h0; out.y = *(unsigned*)&h1;
            out.z = *(unsigned*)&h2; out.w = *(unsigned*)&h3;
            ((uint4*)(g_y + (size_t)v * 64))[sub] = out;
        }
    }
}

// ---------- streaming pool: coalesced y read + per-graph pooling + BN2 stats ----
__global__ __launch_bounds__(256) void k_pool(const int* __restrict__ batch) {
    __shared__ float sS[8][64];
    __shared__ float sQ[8][64];
    int lane = threadIdx.x & 31;
    int wid = threadIdx.x >> 5;
    int gwarp = blockIdx.x * 8 + wid;
    int nwarps = gridDim.x * 8;
    int npw = (NN + nwarps - 1) / nwarps;
    int v0 = gwarp * npw;
    int v1 = min(v0 + npw, NN);
    int f0 = 2 * lane;

    float ps0 = 0.f, ps1 = 0.f;
    float mx0 = -__int_as_float(0x7F800000), mx1 = mx0;
    float mn0 = __int_as_float(0x7F800000), mn1 = mn0;
    float ss0 = 0.f, ss1 = 0.f, sq0 = 0.f, sq1 = 0.f;
    int gcur = -1;

    for (int v = v0; v < v1; v++) {
        float2 f = __half22float2(((const half2*)(g_y + (size_t)v * 64))[lane]);
        int g = batch[v];                 // broadcast load
        if (g != gcur) {
            if (gcur >= 0) {
                int pb = gcur * 64 + f0;
                atomicAdd(&g_psum[pb], ps0);
                atomicAdd(&g_psum[pb + 1], ps1);
                atomicMaxFloat(&g_pmax[pb], mx0);
                atomicMaxFloat(&g_pmax[pb + 1], mx1);
                atomicMinFloat(&g_pmin[pb], mn0);
                atomicMinFloat(&g_pmin[pb + 1], mn1);
            }
            gcur = g;
            ps0 = 0.f; ps1 = 0.f;
            mx0 = -__int_as_float(0x7F800000); mx1 = mx0;
            mn0 = __int_as_float(0x7F800000); mn1 = mn0;
        }
        ps0 += f.x; ps1 += f.y;
        mx0 = fmaxf(mx0, f.x); mx1 = fmaxf(mx1, f.y);
        mn0 = fminf(mn0, f.x); mn1 = fminf(mn1, f.y);
        ss0 += f.x; ss1 += f.y;
        sq0 = fmaf(f.x, f.x, sq0); sq1 = fmaf(f.y, f.y, sq1);
    }
    if (gcur >= 0) {
        int pb = gcur * 64 + f0;
        atomicAdd(&g_psum[pb], ps0);
        atomicAdd(&g_psum[pb + 1], ps1);
        atomicMaxFloat(&g_pmax[pb], mx0);
        atomicMaxFloat(&g_pmax[pb + 1], mx1);
        atomicMinFloat(&g_pmin[pb], mn0);
        atomicMinFloat(&g_pmin[pb + 1], mn1);
    }
    sS[wid][f0] = ss0; sS[wid][f0 + 1] = ss1;
    sQ[wid][f0] = sq0; sQ[wid][f0 + 1] = sq1;
    __syncthreads();
    if (threadIdx.x < 64) {
        float as = 0.f, aq = 0.f;
#pragma unroll
        for (int w = 0; w < 8; w++) { as += sS[w][threadIdx.x]; aq += sQ[w][threadIdx.x]; }
        atomicAdd(&g_s2[threadIdx.x], as);
        atomicAdd(&g_q2[threadIdx.x], aq);
    }
}

// ---------------- finalize ----------------
__global__ void k_final(const float* __restrict__ gamma2, const float* __restrict__ beta2,
                        float* __restrict__ out) {
    int f = threadIdx.x;
    if (f >= 64) return;
    float mu = g_s2[f] / (float)NN;
    float var = g_q2[f] / (float)NN - mu * mu;
    float a = rsqrtf(var + EPS) * gamma2[f];
    float sh = beta2[f] - mu * a;
    for (int g = 0; g < GG; g++) {
        float mx = __int_as_float(g_pmax[g * 64 + f]);
        float mn = __int_as_float(g_pmin[g * 64 + f]);
        float chosen = (a >= 0.f) ? mx : mn;
        out[g * 128 + f] = fmaf(chosen, a, sh);
        float c = fmaxf((float)g_cnt[g], 1.f);
        out[g * 128 + 64 + f] = fmaf(g_psum[g * 64 + f] / c, a, sh);
    }
}

// ---------------- launch ----------------
extern "C" void kernel_launch(void* const* d_in, const int* in_sizes, int n_in,
                              void* d_out, int out_size) {
    const int* node_type = (const int*)d_in[0];
    const int* num_inv   = (const int*)d_in[1];
    const int* edge      = (const int*)d_in[2];
    const int* batch     = (const int*)d_in[3];
    const float* emb_type = (const float*)d_in[4];
    const float* emb_inv  = (const float*)d_in[5];
    const float* W1       = (const float*)d_in[6];
    const float* W2       = (const float*)d_in[8];
    const float* gamma1   = (const float*)d_in[10];
    const float* beta1    = (const float*)d_in[11];
    const float* gamma2   = (const float*)d_in[12];
    const float* beta2    = (const float*)d_in[13];
    float* out = (float*)d_out;

    const int* esrc = edge;
    const int* edst = edge + EE;

    void* pDeg;
    cudaGetSymbolAddress(&pDeg, g_deg);
    cudaMemsetAsync(pDeg, 0, (size_t)NN * sizeof(int));

    k_small_init<<<(GG * 64 + 255) / 256, 256>>>();
    k_cnt<<<1, 64>>>(batch);
    k_prep<<<1, 576>>>(emb_type, emb_inv, W1);
    k_deg<<<(EE + 255) / 256, 256>>>(edst);
    k_dis<<<(NN + 255) / 256, 256>>>(node_type, num_inv);
    k_scan1<<<NBS, SCAN_B>>>();
    k_scan2<<<1, 1024>>>();
    k_scan3<<<NBS, SCAN_B>>>();
    k_scatter_edge1<<<(EE + 255) / 256, 256>>>(esrc, edst);
    k_stats<<<296, 256>>>();
    k_bn1<<<1, 64>>>(gamma1, beta1);
    k_fused1<<<(NN + 127) / 128, 256>>>(W2);
    k_gather<<<1184, 256>>>();
    k_pool<<<296, 256>>>(batch);
    k_final<<<1, 64>>>(gamma2, beta2, out);
}

// round 9
// speedup vs baseline: 1.0937x; 1.0937x over previous
#include <cuda_runtime.h>
#include <cuda_fp16.h>
#include <mma.h>

using namespace nvcuda;

#define NN 500000
#define EE 2000000
#define GG 64
#define EPS 1e-5f
#define SCAN_B 512
#define NBS ((NN + SCAN_B - 1) / SCAN_B)   // 977

// ---------------- scratch (device globals; no allocs allowed) ----------------
__device__ __align__(16) int    g_deg[NN];
__device__ __align__(16) float  g_dis[NN];
__device__ __align__(16) int    g_c[NN];
__device__ __align__(16) int    g_off[NN + 1];
__device__ __align__(16) int    g_cur[NN];
__device__ __align__(16) int    g_bsum[NBS];
__device__ __align__(16) int    g_bpre[NBS];
__device__ __align__(16) int    g_srcs[EE];
__device__ __align__(16) float  g_S[NN * 9];
__device__ __align__(16) __half g_y1[((size_t)NN + 128) * 64];  // dis*(z1@W2) fp16
__device__ __align__(16) __half g_y[(size_t)NN * 64];           // aggregated layer-2 out
__device__ __align__(16) float  g_M1[9 * 64];
__device__ __align__(16) float  g_a1[64];
__device__ __align__(16) float  g_sh1[64];
__device__ __align__(16) float  g_mom[64];
__device__ __align__(16) float  g_s2[64];
__device__ __align__(16) float  g_q2[64];
__device__ __align__(16) float  g_psum[GG * 64];
__device__ __align__(16) int    g_pmax[GG * 64];
__device__ __align__(16) int    g_pmin[GG * 64];
__device__                int    g_cnt[GG];

// ---------------- helpers ----------------
__device__ __forceinline__ void atomicMaxFloat(int* addr, float v) {
    if (v >= 0.0f) atomicMax(addr, __float_as_int(v));
    else           atomicMin((unsigned int*)addr, __float_as_uint(v));
}
__device__ __forceinline__ void atomicMinFloat(int* addr, float v) {
    if (v >= 0.0f) atomicMin(addr, __float_as_int(v));
    else           atomicMax((unsigned int*)addr, __float_as_uint(v));
}

// ---------------- small init ----------------
__global__ void k_small_init() {
    int i = blockIdx.x * blockDim.x + threadIdx.x;
    if (i < GG * 64) {
        g_pmax[i] = 0xFF800000;
        g_pmin[i] = 0x7F800000;
        g_psum[i] = 0.0f;
    }
    if (i < 64) {
        g_mom[i] = 0.0f;
        g_s2[i] = 0.0f; g_q2[i] = 0.0f;
    }
}

// ---------------- per-graph node counts: binary search over sorted batch -----
__global__ void k_cnt(const int* __restrict__ batch) {
    int g = threadIdx.x;
    if (g >= GG) return;
    int lo0 = 0, hi0 = NN;
    while (lo0 < hi0) { int m = (lo0 + hi0) >> 1; if (batch[m] < g) lo0 = m + 1; else hi0 = m; }
    int lo1 = lo0, hi1 = NN;
    while (lo1 < hi1) { int m = (lo1 + hi1) >> 1; if (batch[m] < g + 1) lo1 = m + 1; else hi1 = m; }
    g_cnt[g] = lo1 - lo0;
}

// ---------------- M1 = [emb_type || emb_inv] @ W1  (9 x 64) ----------------
__global__ void k_prep(const float* __restrict__ emb_type,
                       const float* __restrict__ emb_inv,
                       const float* __restrict__ W1) {
    int t = threadIdx.x;
    if (t >= 9 * 64) return;
    int combo = t >> 6;
    int f = t & 63;
    int ty = combo / 3, iv = combo % 3;
    float acc = 0.0f;
#pragma unroll
    for (int k = 0; k < 16; k++) {
        acc = fmaf(emb_type[ty * 16 + k], W1[k * 64 + f], acc);
        acc = fmaf(emb_inv[iv * 16 + k], W1[(16 + k) * 64 + f], acc);
    }
    g_M1[combo * 64 + f] = acc;
}

// ---------------- degree histogram ----------------
__global__ void k_deg(const int* __restrict__ edst) {
    int e = blockIdx.x * blockDim.x + threadIdx.x;
    if (e < EE) atomicAdd(&g_deg[edst[e]], 1);
}

// ---------------- per-node: dis, combo idx, write full S row ----------------
__global__ void k_dis(const int* __restrict__ node_type,
                      const int* __restrict__ num_inv) {
    int v = blockIdx.x * blockDim.x + threadIdx.x;
    if (v >= NN) return;
    int d = g_deg[v] + 1;
    float dis = rsqrtf((float)d);
    g_dis[v] = dis;
    int c = node_type[v] * 3 + num_inv[v];
    g_c[v] = c;
    float id = dis * dis;
#pragma unroll
    for (int t = 0; t < 9; t++) g_S[(size_t)v * 9 + t] = (t == c) ? id : 0.0f;
}

// ---------------- CSR scan (3 stages) ----------------
__global__ __launch_bounds__(SCAN_B) void k_scan1() {
    __shared__ int s[SCAN_B];
    int gid = blockIdx.x * SCAN_B + threadIdx.x;
    int v = (gid < NN) ? g_deg[gid] : 0;
    s[threadIdx.x] = v;
    __syncthreads();
    for (int o = 1; o < SCAN_B; o <<= 1) {
        int x = s[threadIdx.x];
        if (threadIdx.x >= o) x += s[threadIdx.x - o];
        __syncthreads();
        s[threadIdx.x] = x;
        __syncthreads();
    }
    if (threadIdx.x == SCAN_B - 1) g_bsum[blockIdx.x] = s[SCAN_B - 1];
}
__global__ __launch_bounds__(1024) void k_scan2() {
    __shared__ int s[1024];
    int t = threadIdx.x;
    int v = (t < NBS) ? g_bsum[t] : 0;
    s[t] = v;
    __syncthreads();
    for (int o = 1; o < 1024; o <<= 1) {
        int x = s[t];
        if (t >= o) x += s[t - o];
        __syncthreads();
        s[t] = x;
        __syncthreads();
    }
    if (t < NBS) g_bpre[t] = s[t] - v;   // exclusive
}
__global__ __launch_bounds__(SCAN_B) void k_scan3() {
    __shared__ int s[SCAN_B];
    int gid = blockIdx.x * SCAN_B + threadIdx.x;
    int v = (gid < NN) ? g_deg[gid] : 0;
    s[threadIdx.x] = v;
    __syncthreads();
    for (int o = 1; o < SCAN_B; o <<= 1) {
        int x = s[threadIdx.x];
        if (threadIdx.x >= o) x += s[threadIdx.x - o];
        __syncthreads();
        s[threadIdx.x] = x;
        __syncthreads();
    }
    if (gid < NN) {
        int excl = s[threadIdx.x] - v + g_bpre[blockIdx.x];
        g_off[gid] = excl;
        g_cur[gid] = excl;
        if (gid == NN - 1) g_off[NN] = excl + v;
    }
}

// ------- fused: CSR ticket-scatter + layer-1 bucket aggregation ---------------
__global__ void k_scatter_edge1(const int* __restrict__ esrc, const int* __restrict__ edst) {
    int e = blockIdx.x * blockDim.x + threadIdx.x;
    if (e >= EE) return;
    int s = esrc[e], d = edst[e];
    int pos = atomicAdd(&g_cur[d], 1);
    g_srcs[pos] = s;
    atomicAdd(&g_S[(size_t)d * 9 + g_c[s]], g_dis[s] * g_dis[d]);
}

// ---------------- S moments: sum S (9) + upper-tri of sum S S^T (45) ----------
__global__ __launch_bounds__(256) void k_stats() {
    __shared__ float sS[256 * 9];
    __shared__ float sred[8][54];
    float m[54];
#pragma unroll
    for (int i = 0; i < 54; i++) m[i] = 0.0f;

    int tiles = (NN + 255) / 256;
    for (int t = blockIdx.x; t < tiles; t += gridDim.x) {
        int base = t * 256;
        int cnt = min(256, NN - base);
        int tot = cnt * 9;
        __syncthreads();
        for (int i = threadIdx.x; i < tot; i += 256) sS[i] = g_S[(size_t)base * 9 + i];
        __syncthreads();
        if ((int)threadIdx.x < cnt) {
            float r[9];
#pragma unroll
            for (int j = 0; j < 9; j++) r[j] = sS[threadIdx.x * 9 + j];
            int k = 9;
#pragma unroll
            for (int i = 0; i < 9; i++) {
                m[i] += r[i];
#pragma unroll
                for (int j = i; j < 9; j++) { m[k] = fmaf(r[i], r[j], m[k]); k++; }
            }
        }
    }
#pragma unroll
    for (int v = 0; v < 54; v++) {
#pragma unroll
        for (int o = 16; o > 0; o >>= 1) m[v] += __shfl_down_sync(0xffffffffu, m[v], o);
    }
    int lane = threadIdx.x & 31, warp = threadIdx.x >> 5;
    if (lane == 0) {
#pragma unroll
        for (int v = 0; v < 54; v++) sred[warp][v] = m[v];
    }
    __syncthreads();
    if (threadIdx.x < 54) {
        float acc = 0.0f;
#pragma unroll
        for (int w = 0; w < 8; w++) acc += sred[w][threadIdx.x];
        atomicAdd(&g_mom[threadIdx.x], acc);
    }
}

// ---------------- BN1 affine params from moments ----------------
__global__ void k_bn1(const float* __restrict__ gamma1, const float* __restrict__ beta1) {
    int f = threadIdx.x;
    if (f >= 64) return;
    float mcol[9];
#pragma unroll
    for (int t = 0; t < 9; t++) mcol[t] = g_M1[t * 64 + f];
    float mean = 0.0f;
#pragma unroll
    for (int t = 0; t < 9; t++) mean = fmaf(g_mom[t], mcol[t], mean);
    mean /= (float)NN;
    float e2 = 0.0f;
    int k = 9;
#pragma unroll
    for (int i = 0; i < 9; i++) {
#pragma unroll
        for (int j = i; j < 9; j++) {
            float term = g_mom[k++] * mcol[i] * mcol[j];
            e2 += (i == j) ? term : 2.0f * term;
        }
    }
    e2 /= (float)NN;
    float var = e2 - mean * mean;
    float a = rsqrtf(var + EPS) * gamma1[f];
    g_a1[f] = a;
    g_sh1[f] = beta1[f] - mean * a;
}

// -- fused layer1 + GEMM: (dis*z1) tile in smem fp16 -> wmma @ W2 -> y1' fp16 --
// y1'[v] = dis[v] * relu(affine(S@M1)) @ W2
#define ZLD 80
__global__ __launch_bounds__(256) void k_fused1(const float* __restrict__ W2) {
    __shared__ float  sM1[9 * 64];
    __shared__ float  sA[64], sSh[64];
    __shared__ __half sW[64 * 64];
    __shared__ __half sZ[128 * ZLD];

    int tid = threadIdx.x;
    for (int i = tid; i < 9 * 64; i += 256) sM1[i] = g_M1[i];
    if (tid < 64) { sA[tid] = g_a1[tid]; sSh[tid] = g_sh1[tid]; }
    for (int i = tid; i < 64 * 64 / 2; i += 256) {
        float2 w = ((const float2*)W2)[i];
        ((half2*)sW)[i] = __floats2half2_rn(w.x, w.y);
    }
    __syncthreads();

    int base = blockIdx.x * 128;
    {
        int nl = tid >> 1;
        int h = tid & 1;
        int v = base + nl;
        half2* dst = (half2*)(sZ + nl * ZLD + h * 32);
        if (v < NN) {
            float dv = g_dis[v];
            float Sv[9];
#pragma unroll
            for (int t = 0; t < 9; t++) Sv[t] = g_S[(size_t)v * 9 + t];
#pragma unroll
            for (int j = 0; j < 16; j++) {
                int f = h * 32 + 2 * j;
                float y0 = 0.f, y1 = 0.f;
#pragma unroll
                for (int t = 0; t < 9; t++) {
                    y0 = fmaf(Sv[t], sM1[t * 64 + f], y0);
                    y1 = fmaf(Sv[t], sM1[t * 64 + f + 1], y1);
                }
                float z0 = dv * fmaxf(fmaf(y0, sA[f], sSh[f]), 0.f);
                float z1 = dv * fmaxf(fmaf(y1, sA[f + 1], sSh[f + 1]), 0.f);
                dst[j] = __floats2half2_rn(z0, z1);
            }
        } else {
#pragma unroll
            for (int j = 0; j < 16; j++) dst[j] = __floats2half2_rn(0.f, 0.f);
        }
    }
    __syncthreads();

    int w = tid >> 5;
    wmma::fragment<wmma::accumulator, 16, 16, 16, float> cf[4];
#pragma unroll
    for (int n = 0; n < 4; n++) wmma::fill_fragment(cf[n], 0.0f);
#pragma unroll
    for (int k = 0; k < 4; k++) {
        wmma::fragment<wmma::matrix_a, 16, 16, 16, __half, wmma::row_major> af;
        wmma::load_matrix_sync(af, sZ + (w * 16) * ZLD + k * 16, ZLD);
#pragma unroll
        for (int n = 0; n < 4; n++) {
            wmma::fragment<wmma::matrix_b, 16, 16, 16, __half, wmma::row_major> bf;
            wmma::load_matrix_sync(bf, sW + (k * 16) * 64 + n * 16, 64);
            wmma::mma_sync(cf[n], af, bf, cf[n]);
        }
    }
#pragma unroll
    for (int n = 0; n < 4; n++) {
        wmma::fragment<wmma::accumulator, 16, 16, 16, __half> ch;
#pragma unroll
        for (int i = 0; i < cf[n].num_elements; i++) ch.x[i] = __float2half(cf[n].x[i]);
        wmma::store_matrix_sync(g_y1 + ((size_t)base + w * 16) * 64 + n * 16, ch, 64,
                                wmma::mem_row_major);
    }
}

// ---------- layer-2 aggregation: 4 nodes/warp (R7 shape), edge loop unroll x2 --
// y[v] = dis[v] * ( y1'[v] + sum_{s in in(v)} y1'[s] )
__global__ __launch_bounds__(256) void k_gather() {
    int lane = threadIdx.x & 31;
    int sub = lane & 7;                  // 16B chunk (8 feats) of 128B fp16 row
    int grp = lane >> 3;                 // 4 nodes per warp
    int gw = (blockIdx.x * blockDim.x + threadIdx.x) >> 5;
    int nw = (gridDim.x * blockDim.x) >> 5;

    for (int v = gw * 4 + grp; v < NN; v += nw * 4) {
        int off0 = g_off[v], off1 = g_off[v + 1];
        // self term (already dis-scaled inside y1')
        uint4 raw = ((const uint4*)(g_y1 + (size_t)v * 64))[sub];
        float2 p0 = __half22float2(*(half2*)&raw.x);
        float2 p1 = __half22float2(*(half2*)&raw.y);
        float2 p2 = __half22float2(*(half2*)&raw.z);
        float2 p3 = __half22float2(*(half2*)&raw.w);
        float a0 = p0.x, a1 = p0.y, a2 = p1.x, a3 = p1.y;
        float a4 = p2.x, a5 = p2.y, a6 = p3.x, a7 = p3.y;
        int i = off0;
        for (; i + 1 < off1; i += 2) {       // unroll x2: two loads in flight
            int s0 = g_srcs[i];
            int s1 = g_srcs[i + 1];
            uint4 r0 = ((const uint4*)(g_y1 + (size_t)s0 * 64))[sub];
            uint4 r1 = ((const uint4*)(g_y1 + (size_t)s1 * 64))[sub];
            float2 u0 = __half22float2(*(half2*)&r0.x);
            float2 u1 = __half22float2(*(half2*)&r0.y);
            float2 u2 = __half22float2(*(half2*)&r0.z);
            float2 u3 = __half22float2(*(half2*)&r0.w);
            float2 w0 = __half22float2(*(half2*)&r1.x);
            float2 w1 = __half22float2(*(half2*)&r1.y);
            float2 w2 = __half22float2(*(half2*)&r1.z);
            float2 w3 = __half22float2(*(half2*)&r1.w);
            a0 += u0.x + w0.x; a1 += u0.y + w0.y;
            a2 += u1.x + w1.x; a3 += u1.y + w1.y;
            a4 += u2.x + w2.x; a5 += u2.y + w2.y;
            a6 += u3.x + w3.x; a7 += u3.y + w3.y;
        }
        if (i < off1) {
            int s = g_srcs[i];
            uint4 r = ((const uint4*)(g_y1 + (size_t)s * 64))[sub];
            float2 q0 = __half22float2(*(half2*)&r.x);
            float2 q1 = __half22float2(*(half2*)&r.y);
            float2 q2 = __half22float2(*(half2*)&r.z);
            float2 q3 = __half22float2(*(half2*)&r.w);
            a0 += q0.x; a1 += q0.y; a2 += q1.x; a3 += q1.y;
            a4 += q2.x; a5 += q2.y; a6 += q3.x; a7 += q3.y;
        }
        float dv = g_dis[v];
        half2 h0 = __floats2half2_rn(dv * a0, dv * a1);
        half2 h1 = __floats2half2_rn(dv * a2, dv * a3);
        half2 h2 = __floats2half2_rn(dv * a4, dv * a5);
        half2 h3 = __floats2half2_rn(dv * a6, dv * a7);
        uint4 out;
        out.x = *(unsigned*)&h0; out.y = *(unsigned*)&h1;
        out.z = *(unsigned*)&h2; out.w = *(unsigned*)&h3;
        ((uint4*)(g_y + (size_t)v * 64))[sub] = out;
    }
}

// ---------- streaming pool: coalesced y read + per-graph pooling + BN2 stats ----
__global__ __launch_bounds__(256) void k_pool(const int* __restrict__ batch) {
    __shared__ float sS[8][64];
    __shared__ float sQ[8][64];
    int lane = threadIdx.x & 31;
    int wid = threadIdx.x >> 5;
    int gwarp = blockIdx.x * 8 + wid;
    int nwarps = gridDim.x * 8;
    int npw = (NN + nwarps - 1) / nwarps;
    int v0 = gwarp * npw;
    int v1 = min(v0 + npw, NN);
    int f0 = 2 * lane;

    float ps0 = 0.f, ps1 = 0.f;
    float mx0 = -__int_as_float(0x7F800000), mx1 = mx0;
    float mn0 = __int_as_float(0x7F800000), mn1 = mn0;
    float ss0 = 0.f, ss1 = 0.f, sq0 = 0.f, sq1 = 0.f;
    int gcur = -1;

    for (int v = v0; v < v1; v++) {
        float2 f = __half22float2(((const half2*)(g_y + (size_t)v * 64))[lane]);
        int g = batch[v];                 // broadcast load
        if (g != gcur) {
            if (gcur >= 0) {
                int pb = gcur * 64 + f0;
                atomicAdd(&g_psum[pb], ps0);
                atomicAdd(&g_psum[pb + 1], ps1);
                atomicMaxFloat(&g_pmax[pb], mx0);
                atomicMaxFloat(&g_pmax[pb + 1], mx1);
                atomicMinFloat(&g_pmin[pb], mn0);
                atomicMinFloat(&g_pmin[pb + 1], mn1);
            }
            gcur = g;
            ps0 = 0.f; ps1 = 0.f;
            mx0 = -__int_as_float(0x7F800000); mx1 = mx0;
            mn0 = __int_as_float(0x7F800000); mn1 = mn0;
        }
        ps0 += f.x; ps1 += f.y;
        mx0 = fmaxf(mx0, f.x); mx1 = fmaxf(mx1, f.y);
        mn0 = fminf(mn0, f.x); mn1 = fminf(mn1, f.y);
        ss0 += f.x; ss1 += f.y;
        sq0 = fmaf(f.x, f.x, sq0); sq1 = fmaf(f.y, f.y, sq1);
    }
    if (gcur >= 0) {
        int pb = gcur * 64 + f0;
        atomicAdd(&g_psum[pb], ps0);
        atomicAdd(&g_psum[pb + 1], ps1);
        atomicMaxFloat(&g_pmax[pb], mx0);
        atomicMaxFloat(&g_pmax[pb + 1], mx1);
        atomicMinFloat(&g_pmin[pb], mn0);
        atomicMinFloat(&g_pmin[pb + 1], mn1);
    }
    sS[wid][f0] = ss0; sS[wid][f0 + 1] = ss1;
    sQ[wid][f0] = sq0; sQ[wid][f0 + 1] = sq1;
    __syncthreads();
    if (threadIdx.x < 64) {
        float as = 0.f, aq = 0.f;
#pragma unroll
        for (int w = 0; w < 8; w++) { as += sS[w][threadIdx.x]; aq += sQ[w][threadIdx.x]; }
        atomicAdd(&g_s2[threadIdx.x], as);
        atomicAdd(&g_q2[threadIdx.x], aq);
    }
}

// ---------------- finalize ----------------
__global__ void k_final(const float* __restrict__ gamma2, const float* __restrict__ beta2,
                        float* __restrict__ out) {
    int f = threadIdx.x;
    if (f >= 64) return;
    float mu = g_s2[f] / (float)NN;
    float var = g_q2[f] / (float)NN - mu * mu;
    float a = rsqrtf(var + EPS) * gamma2[f];
    float sh = beta2[f] - mu * a;
    for (int g = 0; g < GG; g++) {
        float mx = __int_as_float(g_pmax[g * 64 + f]);
        float mn = __int_as_float(g_pmin[g * 64 + f]);
        float chosen = (a >= 0.f) ? mx : mn;
        out[g * 128 + f] = fmaf(chosen, a, sh);
        float c = fmaxf((float)g_cnt[g], 1.f);
        out[g * 128 + 64 + f] = fmaf(g_psum[g * 64 + f] / c, a, sh);
    }
}

// ---------------- launch ----------------
extern "C" void kernel_launch(void* const* d_in, const int* in_sizes, int n_in,
                              void* d_out, int out_size) {
    const int* node_type = (const int*)d_in[0];
    const int* num_inv   = (const int*)d_in[1];
    const int* edge      = (const int*)d_in[2];
    const int* batch     = (const int*)d_in[3];
    const float* emb_type = (const float*)d_in[4];
    const float* emb_inv  = (const float*)d_in[5];
    const float* W1       = (const float*)d_in[6];
    const float* W2       = (const float*)d_in[8];
    const float* gamma1   = (const float*)d_in[10];
    const float* beta1    = (const float*)d_in[11];
    const float* gamma2   = (const float*)d_in[12];
    const float* beta2    = (const float*)d_in[13];
    float* out = (float*)d_out;

    const int* esrc = edge;
    const int* edst = edge + EE;

    void* pDeg;
    cudaGetSymbolAddress(&pDeg, g_deg);
    cudaMemsetAsync(pDeg, 0, (size_t)NN * sizeof(int));

    k_small_init<<<(GG * 64 + 255) / 256, 256>>>();
    k_cnt<<<1, 64>>>(batch);
    k_prep<<<1, 576>>>(emb_type, emb_inv, W1);
    k_deg<<<(EE + 255) / 256, 256>>>(edst);
    k_dis<<<(NN + 255) / 256, 256>>>(node_type, num_inv);
    k_scan1<<<NBS, SCAN_B>>>();
    k_scan2<<<1, 1024>>>();
    k_scan3<<<NBS, SCAN_B>>>();
    k_scatter_edge1<<<(EE + 255) / 256, 256>>>(esrc, edst);
    k_stats<<<296, 256>>>();
    k_bn1<<<1, 64>>>(gamma1, beta1);
    k_fused1<<<(NN + 127) / 128, 256>>>(W2);
    k_gather<<<1184, 256>>>();
    k_pool<<<296, 256>>>(batch);
    k_final<<<1, 64>>>(gamma2, beta2, out);
}

// round 10
// speedup vs baseline: 1.1396x; 1.0420x over previous
#include <cuda_runtime.h>
#include <cuda_fp16.h>
#include <mma.h>

using namespace nvcuda;

#define NN 500000
#define EE 2000000
#define GG 64
#define EPS 1e-5f
#define SCAN_B 512
#define NBS ((NN + SCAN_B - 1) / SCAN_B)   // 977
#define NBD ((EE + 255) / 256)             // 7813

// ---------------- scratch (device globals; no allocs allowed) ----------------
__device__ __align__(16) int    g_deg[NN];
__device__ __align__(16) float  g_dis[NN];
__device__ __align__(16) int2   g_dc[NN];          // {dis bits, combo}
__device__ __align__(16) int    g_off[NN + 1];
__device__ __align__(16) int    g_cur[NN];
__device__ __align__(16) int    g_bsum[NBS];
__device__ __align__(16) int    g_srcs[EE];
__device__ __align__(16) float  g_S[NN * 9];
__device__ __align__(16) __half g_y1[((size_t)NN + 128) * 64];  // dis*(z1@W2) fp16
__device__ __align__(16) __half g_y[(size_t)NN * 64];           // aggregated layer-2 out
__device__ __align__(16) float  g_M1[9 * 64];
__device__ __align__(16) float  g_mom[64];
__device__ __align__(16) float  g_s2[64];
__device__ __align__(16) float  g_q2[64];
__device__ __align__(16) float  g_psum[GG * 64];
__device__ __align__(16) int    g_pmax[GG * 64];
__device__ __align__(16) int    g_pmin[GG * 64];
__device__                int    g_cnt[GG];

// ---------------- helpers ----------------
__device__ __forceinline__ void atomicMaxFloat(int* addr, float v) {
    if (v >= 0.0f) atomicMax(addr, __float_as_int(v));
    else           atomicMin((unsigned int*)addr, __float_as_uint(v));
}
__device__ __forceinline__ void atomicMinFloat(int* addr, float v) {
    if (v >= 0.0f) atomicMin(addr, __float_as_int(v));
    else           atomicMax((unsigned int*)addr, __float_as_uint(v));
}

// ======= kernel 1: degree histogram + all small init + cnt + M1 prep =========
__global__ void k_init_deg(const int* __restrict__ edst,
                           const int* __restrict__ batch,
                           const float* __restrict__ emb_type,
                           const float* __restrict__ emb_inv,
                           const float* __restrict__ W1) {
    int b = blockIdx.x;
    int tid = threadIdx.x;
    if (b < NBD) {
        int e = b * 256 + tid;
        if (e < EE) atomicAdd(&g_deg[edst[e]], 1);
        return;
    }
    int extra = b - NBD;
    if (extra == 0) {
        // pool buffers + stat accumulators
        for (int i = tid; i < GG * 64; i += 256) {
            g_pmax[i] = 0xFF800000;
            g_pmin[i] = 0x7F800000;
            g_psum[i] = 0.0f;
        }
        if (tid < 64) { g_mom[tid] = 0.0f; g_s2[tid] = 0.0f; g_q2[tid] = 0.0f; }
    } else if (extra == 1) {
        // per-graph counts via binary search (batch sorted)
        int g = tid;
        if (g < GG) {
            int lo0 = 0, hi0 = NN;
            while (lo0 < hi0) { int m = (lo0 + hi0) >> 1; if (batch[m] < g) lo0 = m + 1; else hi0 = m; }
            int lo1 = lo0, hi1 = NN;
            while (lo1 < hi1) { int m = (lo1 + hi1) >> 1; if (batch[m] < g + 1) lo1 = m + 1; else hi1 = m; }
            g_cnt[g] = lo1 - lo0;
        }
    } else {
        // M1 = [emb_type || emb_inv] @ W1  (9 x 64)
        for (int t = tid; t < 9 * 64; t += 256) {
            int combo = t >> 6;
            int f = t & 63;
            int ty = combo / 3, iv = combo % 3;
            float acc = 0.0f;
#pragma unroll
            for (int k = 0; k < 16; k++) {
                acc = fmaf(emb_type[ty * 16 + k], W1[k * 64 + f], acc);
                acc = fmaf(emb_inv[iv * 16 + k], W1[(16 + k) * 64 + f], acc);
            }
            g_M1[combo * 64 + f] = acc;
        }
    }
}

// ======= kernel 2: per-node dis/dc/S-row + block-scan of deg (scan stage 1) ==
__global__ __launch_bounds__(SCAN_B) void k_dis_scan1(const int* __restrict__ node_type,
                                                      const int* __restrict__ num_inv) {
    __shared__ int s[SCAN_B];
    int gid = blockIdx.x * SCAN_B + threadIdx.x;
    int dval = (gid < NN) ? g_deg[gid] : 0;
    if (gid < NN) {
        int d = dval + 1;                       // + self loop
        float dis = rsqrtf((float)d);
        g_dis[gid] = dis;
        int c = node_type[gid] * 3 + num_inv[gid];
        g_dc[gid] = make_int2(__float_as_int(dis), c);
        float id = dis * dis;
#pragma unroll
        for (int t = 0; t < 9; t++) g_S[(size_t)gid * 9 + t] = (t == c) ? id : 0.0f;
    }
    s[threadIdx.x] = dval;
    __syncthreads();
    for (int o = 1; o < SCAN_B; o <<= 1) {
        int x = s[threadIdx.x];
        if (threadIdx.x >= o) x += s[threadIdx.x - o];
        __syncthreads();
        s[threadIdx.x] = x;
        __syncthreads();
    }
    if (threadIdx.x == SCAN_B - 1) g_bsum[blockIdx.x] = s[SCAN_B - 1];
}

// ======= kernel 3: fused scan stages 2+3 (redundant cross-block prefix) ======
__global__ __launch_bounds__(SCAN_B) void k_scan23() {
    __shared__ int s[SCAN_B];
    __shared__ int red[SCAN_B];
    // bpre = sum of bsum[j] for j < blockIdx.x (each block computes its own)
    int acc = 0;
    for (int j = threadIdx.x; j < blockIdx.x; j += SCAN_B) acc += g_bsum[j];
    red[threadIdx.x] = acc;
    __syncthreads();
    for (int o = SCAN_B / 2; o > 0; o >>= 1) {
        if ((int)threadIdx.x < o) red[threadIdx.x] += red[threadIdx.x + o];
        __syncthreads();
    }
    int bpre = red[0];

    int gid = blockIdx.x * SCAN_B + threadIdx.x;
    int dval = (gid < NN) ? g_deg[gid] : 0;
    s[threadIdx.x] = dval;
    __syncthreads();
    for (int o = 1; o < SCAN_B; o <<= 1) {
        int x = s[threadIdx.x];
        if (threadIdx.x >= o) x += s[threadIdx.x - o];
        __syncthreads();
        s[threadIdx.x] = x;
        __syncthreads();
    }
    if (gid < NN) {
        int excl = s[threadIdx.x] - dval + bpre;
        g_off[gid] = excl;
        g_cur[gid] = excl;
        if (gid == NN - 1) g_off[NN] = excl + dval;
    }
}

// ======= kernel 4: CSR ticket-scatter + layer-1 bucket aggregation ===========
__global__ void k_scatter_edge1(const int* __restrict__ esrc, const int* __restrict__ edst) {
    int e = blockIdx.x * blockDim.x + threadIdx.x;
    if (e >= EE) return;
    int s = esrc[e], d = edst[e];
    int2 ds = __ldg(&g_dc[s]);
    int2 dd = __ldg(&g_dc[d]);
    int pos = atomicAdd(&g_cur[d], 1);
    g_srcs[pos] = s;
    atomicAdd(&g_S[(size_t)d * 9 + ds.y], __int_as_float(ds.x) * __int_as_float(dd.x));
}

// ======= kernel 5: S moments: sum S (9) + upper-tri of sum S S^T (45) ========
__global__ __launch_bounds__(256) void k_stats() {
    __shared__ float sS[256 * 9];
    __shared__ float sred[8][54];
    float m[54];
#pragma unroll
    for (int i = 0; i < 54; i++) m[i] = 0.0f;

    int tiles = (NN + 255) / 256;
    for (int t = blockIdx.x; t < tiles; t += gridDim.x) {
        int base = t * 256;
        int cnt = min(256, NN - base);
        int tot = cnt * 9;
        __syncthreads();
        for (int i = threadIdx.x; i < tot; i += 256) sS[i] = g_S[(size_t)base * 9 + i];
        __syncthreads();
        if ((int)threadIdx.x < cnt) {
            float r[9];
#pragma unroll
            for (int j = 0; j < 9; j++) r[j] = sS[threadIdx.x * 9 + j];
            int k = 9;
#pragma unroll
            for (int i = 0; i < 9; i++) {
                m[i] += r[i];
#pragma unroll
                for (int j = i; j < 9; j++) { m[k] = fmaf(r[i], r[j], m[k]); k++; }
            }
        }
    }
#pragma unroll
    for (int v = 0; v < 54; v++) {
#pragma unroll
        for (int o = 16; o > 0; o >>= 1) m[v] += __shfl_down_sync(0xffffffffu, m[v], o);
    }
    int lane = threadIdx.x & 31, warp = threadIdx.x >> 5;
    if (lane == 0) {
#pragma unroll
        for (int v = 0; v < 54; v++) sred[warp][v] = m[v];
    }
    __syncthreads();
    if (threadIdx.x < 54) {
        float acc = 0.0f;
#pragma unroll
        for (int w = 0; w < 8; w++) acc += sred[w][threadIdx.x];
        atomicAdd(&g_mom[threadIdx.x], acc);
    }
}

// ======= kernel 6: fused BN1 + layer1 + wmma GEMM -> y1' fp16 ================
// y1'[v] = dis[v] * relu(affine(S@M1)) @ W2   (BN1 affine computed per block)
#define ZLD 80
__global__ __launch_bounds__(256) void k_fused1(const float* __restrict__ W2,
                                                const float* __restrict__ gamma1,
                                                const float* __restrict__ beta1) {
    __shared__ float  sM1[9 * 64];
    __shared__ float  sA[64], sSh[64];
    __shared__ __half sW[64 * 64];
    __shared__ __half sZ[128 * ZLD];

    int tid = threadIdx.x;
    for (int i = tid; i < 9 * 64; i += 256) sM1[i] = g_M1[i];
    for (int i = tid; i < 64 * 64 / 2; i += 256) {
        float2 w = ((const float2*)W2)[i];
        ((half2*)sW)[i] = __floats2half2_rn(w.x, w.y);
    }
    __syncthreads();       // sM1 ready (bn1 below reads it from smem)

    if (tid < 64) {        // per-block BN1 affine (redundant but launch-free)
        int f = tid;
        float mcol[9];
#pragma unroll
        for (int t = 0; t < 9; t++) mcol[t] = sM1[t * 64 + f];
        float mean = 0.0f;
#pragma unroll
        for (int t = 0; t < 9; t++) mean = fmaf(g_mom[t], mcol[t], mean);
        mean /= (float)NN;
        float e2 = 0.0f;
        int k = 9;
#pragma unroll
        for (int i = 0; i < 9; i++) {
#pragma unroll
            for (int j = i; j < 9; j++) {
                float term = g_mom[k++] * mcol[i] * mcol[j];
                e2 += (i == j) ? term : 2.0f * term;
            }
        }
        e2 /= (float)NN;
        float var = e2 - mean * mean;
        float a = rsqrtf(var + EPS) * gamma1[f];
        sA[f] = a;
        sSh[f] = beta1[f] - mean * a;
    }
    __syncthreads();

    int base = blockIdx.x * 128;
    {
        int nl = tid >> 1;
        int h = tid & 1;
        int v = base + nl;
        half2* dst = (half2*)(sZ + nl * ZLD + h * 32);
        if (v < NN) {
            float dv = g_dis[v];
            float Sv[9];
#pragma unroll
            for (int t = 0; t < 9; t++) Sv[t] = g_S[(size_t)v * 9 + t];
#pragma unroll
            for (int j = 0; j < 16; j++) {
                int f = h * 32 + 2 * j;
                float y0 = 0.f, y1 = 0.f;
#pragma unroll
                for (int t = 0; t < 9; t++) {
                    y0 = fmaf(Sv[t], sM1[t * 64 + f], y0);
                    y1 = fmaf(Sv[t], sM1[t * 64 + f + 1], y1);
                }
                float z0 = dv * fmaxf(fmaf(y0, sA[f], sSh[f]), 0.f);
                float z1 = dv * fmaxf(fmaf(y1, sA[f + 1], sSh[f + 1]), 0.f);
                dst[j] = __floats2half2_rn(z0, z1);
            }
        } else {
#pragma unroll
            for (int j = 0; j < 16; j++) dst[j] = __floats2half2_rn(0.f, 0.f);
        }
    }
    __syncthreads();

    int w = tid >> 5;
    wmma::fragment<wmma::accumulator, 16, 16, 16, float> cf[4];
#pragma unroll
    for (int n = 0; n < 4; n++) wmma::fill_fragment(cf[n], 0.0f);
#pragma unroll
    for (int k = 0; k < 4; k++) {
        wmma::fragment<wmma::matrix_a, 16, 16, 16, __half, wmma::row_major> af;
        wmma::load_matrix_sync(af, sZ + (w * 16) * ZLD + k * 16, ZLD);
#pragma unroll
        for (int n = 0; n < 4; n++) {
            wmma::fragment<wmma::matrix_b, 16, 16, 16, __half, wmma::row_major> bf;
            wmma::load_matrix_sync(bf, sW + (k * 16) * 64 + n * 16, 64);
            wmma::mma_sync(cf[n], af, bf, cf[n]);
        }
    }
#pragma unroll
    for (int n = 0; n < 4; n++) {
        wmma::fragment<wmma::accumulator, 16, 16, 16, __half> ch;
#pragma unroll
        for (int i = 0; i < cf[n].num_elements; i++) ch.x[i] = __float2half(cf[n].x[i]);
        wmma::store_matrix_sync(g_y1 + ((size_t)base + w * 16) * 64 + n * 16, ch, 64,
                                wmma::mem_row_major);
    }
}

// ======= kernel 7: CSR gather, 4 nodes/warp, unroll x2, streaming y write ====
// y[v] = dis[v] * ( y1'[v] + sum_{s in in(v)} y1'[s] )
__global__ __launch_bounds__(256) void k_gather() {
    int lane = threadIdx.x & 31;
    int sub = lane & 7;
    int grp = lane >> 3;
    int gw = (blockIdx.x * blockDim.x + threadIdx.x) >> 5;
    int nw = (gridDim.x * blockDim.x) >> 5;

    for (int v = gw * 4 + grp; v < NN; v += nw * 4) {
        int off0 = __ldg(&g_off[v]), off1 = __ldg(&g_off[v + 1]);
        uint4 raw = ((const uint4*)(g_y1 + (size_t)v * 64))[sub];
        float2 p0 = __half22float2(*(half2*)&raw.x);
        float2 p1 = __half22float2(*(half2*)&raw.y);
        float2 p2 = __half22float2(*(half2*)&raw.z);
        float2 p3 = __half22float2(*(half2*)&raw.w);
        float a0 = p0.x, a1 = p0.y, a2 = p1.x, a3 = p1.y;
        float a4 = p2.x, a5 = p2.y, a6 = p3.x, a7 = p3.y;
        int i = off0;
        for (; i + 1 < off1; i += 2) {
            int s0 = __ldg(&g_srcs[i]);
            int s1 = __ldg(&g_srcs[i + 1]);
            uint4 r0 = ((const uint4*)(g_y1 + (size_t)s0 * 64))[sub];
            uint4 r1 = ((const uint4*)(g_y1 + (size_t)s1 * 64))[sub];
            float2 u0 = __half22float2(*(half2*)&r0.x);
            float2 u1 = __half22float2(*(half2*)&r0.y);
            float2 u2 = __half22float2(*(half2*)&r0.z);
            float2 u3 = __half22float2(*(half2*)&r0.w);
            float2 w0 = __half22float2(*(half2*)&r1.x);
            float2 w1 = __half22float2(*(half2*)&r1.y);
            float2 w2 = __half22float2(*(half2*)&r1.z);
            float2 w3 = __half22float2(*(half2*)&r1.w);
            a0 += u0.x + w0.x; a1 += u0.y + w0.y;
            a2 += u1.x + w1.x; a3 += u1.y + w1.y;
            a4 += u2.x + w2.x; a5 += u2.y + w2.y;
            a6 += u3.x + w3.x; a7 += u3.y + w3.y;
        }
        if (i < off1) {
            int s = __ldg(&g_srcs[i]);
            uint4 r = ((const uint4*)(g_y1 + (size_t)s * 64))[sub];
            float2 q0 = __half22float2(*(half2*)&r.x);
            float2 q1 = __half22float2(*(half2*)&r.y);
            float2 q2 = __half22float2(*(half2*)&r.z);
            float2 q3 = __half22float2(*(half2*)&r.w);
            a0 += q0.x; a1 += q0.y; a2 += q1.x; a3 += q1.y;
            a4 += q2.x; a5 += q2.y; a6 += q3.x; a7 += q3.y;
        }
        float dv = g_dis[v];
        half2 h0 = __floats2half2_rn(dv * a0, dv * a1);
        half2 h1 = __floats2half2_rn(dv * a2, dv * a3);
        half2 h2 = __floats2half2_rn(dv * a4, dv * a5);
        half2 h3 = __floats2half2_rn(dv * a6, dv * a7);
        int4 out;
        out.x = *(int*)&h0; out.y = *(int*)&h1;
        out.z = *(int*)&h2; out.w = *(int*)&h3;
        __stcs((int4*)(g_y + (size_t)v * 64) + sub, out);   // evict-first: keep y1 in L2
    }
}

// ======= kernel 8: streaming pool + BN2 stats ================================
__global__ __launch_bounds__(256) void k_pool(const int* __restrict__ batch) {
    __shared__ float sS[8][64];
    __shared__ float sQ[8][64];
    int lane = threadIdx.x & 31;
    int wid = threadIdx.x >> 5;
    int gwarp = blockIdx.x * 8 + wid;
    int nwarps = gridDim.x * 8;
    int npw = (NN + nwarps - 1) / nwarps;
    int v0 = gwarp * npw;
    int v1 = min(v0 + npw, NN);
    int f0 = 2 * lane;

    float ps0 = 0.f, ps1 = 0.f;
    float mx0 = -__int_as_float(0x7F800000), mx1 = mx0;
    float mn0 = __int_as_float(0x7F800000), mn1 = mn0;
    float ss0 = 0.f, ss1 = 0.f, sq0 = 0.f, sq1 = 0.f;
    int gcur = -1;

    for (int v = v0; v < v1; v++) {
        unsigned int bits = __ldcs((const unsigned int*)(g_y + (size_t)v * 64) + lane);
        float2 f = __half22float2(*(half2*)&bits);
        int g = batch[v];
        if (g != gcur) {
            if (gcur >= 0) {
                int pb = gcur * 64 + f0;
                atomicAdd(&g_psum[pb], ps0);
                atomicAdd(&g_psum[pb + 1], ps1);
                atomicMaxFloat(&g_pmax[pb], mx0);
                atomicMaxFloat(&g_pmax[pb + 1], mx1);
                atomicMinFloat(&g_pmin[pb], mn0);
                atomicMinFloat(&g_pmin[pb + 1], mn1);
            }
            gcur = g;
            ps0 = 0.f; ps1 = 0.f;
            mx0 = -__int_as_float(0x7F800000); mx1 = mx0;
            mn0 = __int_as_float(0x7F800000); mn1 = mn0;
        }
        ps0 += f.x; ps1 += f.y;
        mx0 = fmaxf(mx0, f.x); mx1 = fmaxf(mx1, f.y);
        mn0 = fminf(mn0, f.x); mn1 = fminf(mn1, f.y);
        ss0 += f.x; ss1 += f.y;
        sq0 = fmaf(f.x, f.x, sq0); sq1 = fmaf(f.y, f.y, sq1);
    }
    if (gcur >= 0) {
        int pb = gcur * 64 + f0;
        atomicAdd(&g_psum[pb], ps0);
        atomicAdd(&g_psum[pb + 1], ps1);
        atomicMaxFloat(&g_pmax[pb], mx0);
        atomicMaxFloat(&g_pmax[pb + 1], mx1);
        atomicMinFloat(&g_pmin[pb], mn0);
        atomicMinFloat(&g_pmin[pb + 1], mn1);
    }
    sS[wid][f0] = ss0; sS[wid][f0 + 1] = ss1;
    sQ[wid][f0] = sq0; sQ[wid][f0 + 1] = sq1;
    __syncthreads();
    if (threadIdx.x < 64) {
        float as = 0.f, aq = 0.f;
#pragma unroll
        for (int w = 0; w < 8; w++) { as += sS[w][threadIdx.x]; aq += sQ[w][threadIdx.x]; }
        atomicAdd(&g_s2[threadIdx.x], as);
        atomicAdd(&g_q2[threadIdx.x], aq);
    }
}

// ======= kernel 9: finalize ===================================================
__global__ void k_final(const float* __restrict__ gamma2, const float* __restrict__ beta2,
                        float* __restrict__ out) {
    int f = threadIdx.x;
    if (f >= 64) return;
    float mu = g_s2[f] / (float)NN;
    float var = g_q2[f] / (float)NN - mu * mu;
    float a = rsqrtf(var + EPS) * gamma2[f];
    float sh = beta2[f] - mu * a;
    for (int g = 0; g < GG; g++) {
        float mx = __int_as_float(g_pmax[g * 64 + f]);
        float mn = __int_as_float(g_pmin[g * 64 + f]);
        float chosen = (a >= 0.f) ? mx : mn;
        out[g * 128 + f] = fmaf(chosen, a, sh);
        float c = fmaxf((float)g_cnt[g], 1.f);
        out[g * 128 + 64 + f] = fmaf(g_psum[g * 64 + f] / c, a, sh);
    }
}

// ---------------- launch ----------------
extern "C" void kernel_launch(void* const* d_in, const int* in_sizes, int n_in,
                              void* d_out, int out_size) {
    const int* node_type = (const int*)d_in[0];
    const int* num_inv   = (const int*)d_in[1];
    const int* edge      = (const int*)d_in[2];
    const int* batch     = (const int*)d_in[3];
    const float* emb_type = (const float*)d_in[4];
    const float* emb_inv  = (const float*)d_in[5];
    const float* W1       = (const float*)d_in[6];
    const float* W2       = (const float*)d_in[8];
    const float* gamma1   = (const float*)d_in[10];
    const float* beta1    = (const float*)d_in[11];
    const float* gamma2   = (const float*)d_in[12];
    const float* beta2    = (const float*)d_in[13];
    float* out = (float*)d_out;

    const int* esrc = edge;
    const int* edst = edge + EE;

    void* pDeg;
    cudaGetSymbolAddress(&pDeg, g_deg);
    cudaMemsetAsync(pDeg, 0, (size_t)NN * sizeof(int));

    k_init_deg<<<NBD + 3, 256>>>(edst, batch, emb_type, emb_inv, W1);
    k_dis_scan1<<<NBS, SCAN_B>>>(node_type, num_inv);
    k_scan23<<<NBS, SCAN_B>>>();
    k_scatter_edge1<<<NBD, 256>>>(esrc, edst);
    k_stats<<<296, 256>>>();
    k_fused1<<<(NN + 127) / 128, 256>>>(W2, gamma1, beta1);
    k_gather<<<1184, 256>>>();
    k_pool<<<296, 256>>>(batch);
    k_final<<<1, 64>>>(gamma2, beta2, out);
}